// round 16
// baseline (speedup 1.0000x reference)
#include <cuda_runtime.h>
#include <cuda_bf16.h>
#include <math.h>
#include <cstdint>

#define BATCH   131072
#define DIM     64
#define QD      32
#define NLAYERS 6
#define HF      128
#define HH      256
#define DTC     0.05f

// ===========================================================================
// Pair-interleaved K layout (proven round 15): fragment pairs adjacent.
// ===========================================================================
__host__ __device__ __forceinline__ int ipos(int k) {
    return (k & ~15) | (((k >> 1) & 3) << 2) | ((k & 8) >> 2) | (k & 1);
}

// ===========================================================================
// Scratch (static __device__ arrays)
// ===========================================================================
__device__ __align__(16) float g_z   [BATCH * DIM];
__device__ __align__(16) float g_acc [BATCH * DIM];
__device__ __align__(16) __nv_bfloat16 g_zk [BATCH * DIM];       // k-interleaved
__device__ __align__(16) __nv_bfloat16 g_h1T[BATCH * HH];        // k-interleaved
__device__ __align__(16) __nv_bfloat16 g_h1V[BATCH * HH];
__device__ __align__(16) __nv_bfloat16 g_g2T[BATCH * HH];
__device__ __align__(16) __nv_bfloat16 g_g2V[BATCH * HH];
__device__ __align__(16) __nv_bfloat16 g_g1T[BATCH * HH];
__device__ __align__(16) __nv_bfloat16 g_g1V[BATCH * HH];
// bf16 weight images, row-major [N][K], K pair-interleaved
__device__ __align__(16) __nv_bfloat16 g_Bk1  [HH * 64];
__device__ __align__(16) __nv_bfloat16 g_Bv1  [HH * 64];
__device__ __align__(16) __nv_bfloat16 g_Bk2  [HH * HH];
__device__ __align__(16) __nv_bfloat16 g_Bv2  [HH * HH];
__device__ __align__(16) __nv_bfloat16 g_Bk2t [HH * HH];
__device__ __align__(16) __nv_bfloat16 g_Bv2t [HH * HH];
__device__ __align__(16) __nv_bfloat16 g_BMcat[64 * 512];
__device__ float g_M[DIM * DIM];
// flow weights, tf32-rounded (natural layout)
__device__ __align__(16) float g_fpk[NLAYERS * 16384];

__device__ __forceinline__ float softplusf(float x) {
    return fmaxf(x, 0.f) + log1pf(expf(-fabsf(x)));
}
__device__ __forceinline__ float softplus_fast(float x) {
    return fmaxf(x, 0.f) + __logf(1.f + __expf(-fabsf(x)));
}

__device__ __forceinline__ uint32_t smem_u32(const void* p) {
    uint32_t a;
    asm("{ .reg .u64 t; cvta.to.shared.u64 t, %1; cvt.u32.u64 %0, t; }"
        : "=r"(a) : "l"(p));
    return a;
}

// VOLATILE shared loads (no CSE across barriers)
__device__ __forceinline__ uint32_t lds32(uint32_t addr) {
    uint32_t v;
    asm volatile("ld.shared.b32 %0, [%1];" : "=r"(v) : "r"(addr));
    return v;
}
__device__ __forceinline__ void lds64(uint32_t addr, uint32_t& x, uint32_t& y) {
    asm volatile("ld.shared.v2.b32 {%0, %1}, [%2];" : "=r"(x), "=r"(y) : "r"(addr));
}
__device__ __forceinline__ void sts32(uint32_t addr, uint32_t v) {
    asm volatile("st.shared.b32 [%0], %1;" :: "r"(addr), "r"(v));
}

__device__ __forceinline__ float tf32r(float x) {
    uint32_t u;
    asm("cvt.rna.tf32.f32 %0, %1;" : "=r"(u) : "f"(x));
    return __uint_as_float(u);
}

__device__ __forceinline__ void cpasync16(uint32_t dst, const void* src) {
    asm volatile("cp.async.cg.shared.global [%0], [%1], 16;"
                 :: "r"(dst), "l"(src));
}
__device__ __forceinline__ void cp_commit() {
    asm volatile("cp.async.commit_group;");
}
template<int N>
__device__ __forceinline__ void cp_wait() {
    asm volatile("cp.async.wait_group %0;" :: "n"(N));
}

__device__ __forceinline__ void mma16816(float* c, uint32_t a0, uint32_t a1,
                                         uint32_t a2, uint32_t a3,
                                         uint32_t b0, uint32_t b1) {
    asm volatile(
        "mma.sync.aligned.m16n8k16.row.col.f32.bf16.bf16.f32 "
        "{%0,%1,%2,%3},{%4,%5,%6,%7},{%8,%9},{%0,%1,%2,%3};"
        : "+f"(c[0]), "+f"(c[1]), "+f"(c[2]), "+f"(c[3])
        : "r"(a0), "r"(a1), "r"(a2), "r"(a3), "r"(b0), "r"(b1));
}

__device__ __forceinline__ void mma_tf32(float* c, uint32_t a0, uint32_t a1,
                                         uint32_t a2, uint32_t a3,
                                         uint32_t b0, uint32_t b1) {
    asm volatile(
        "mma.sync.aligned.m16n8k8.row.col.f32.tf32.tf32.f32 "
        "{%0,%1,%2,%3},{%4,%5,%6,%7},{%8,%9},{%0,%1,%2,%3};"
        : "+f"(c[0]), "+f"(c[1]), "+f"(c[2]), "+f"(c[3])
        : "r"(a0), "r"(a1), "r"(a2), "r"(a3), "r"(b0), "r"(b1));
}

// ===========================================================================
// Prep kernels
// ===========================================================================
__global__ void build_M_k(const float* __restrict__ A, const float* __restrict__ Lp,
                          float* __restrict__ M) {
    __shared__ float L[DIM * DIM];
    int t = threadIdx.x;
    for (int idx = t; idx < DIM * DIM; idx += 256) {
        int i = idx >> 6, j = idx & 63;
        float v;
        if (i > j)       v = Lp[idx];
        else if (i == j) v = softplusf(Lp[idx]);
        else             v = 0.f;
        L[idx] = v;
    }
    __syncthreads();
    for (int idx = t; idx < DIM * DIM; idx += 256) {
        int i = idx >> 6, j = idx & 63;
        float s = 0.f;
        #pragma unroll 8
        for (int k = 0; k < DIM; k++) s += L[i * DIM + k] * L[j * DIM + k];
        M[idx] = A[i * DIM + j] - A[j * DIM + i] - s;
    }
}

__global__ void prep_pack_k(const float* __restrict__ kW1, const float* __restrict__ vW1,
                            const float* __restrict__ kW2, const float* __restrict__ vW2,
                            const float* __restrict__ M,
                            const float* __restrict__ sW1, const float* __restrict__ sW2,
                            const float* __restrict__ tW1, const float* __restrict__ tW2,
                            __nv_bfloat16* __restrict__ Bk1, __nv_bfloat16* __restrict__ Bv1,
                            __nv_bfloat16* __restrict__ Bk2, __nv_bfloat16* __restrict__ Bv2,
                            __nv_bfloat16* __restrict__ Bk2t, __nv_bfloat16* __restrict__ Bv2t,
                            __nv_bfloat16* __restrict__ BMcat,
                            float* __restrict__ fpk) {
    int idx = blockIdx.x * 256 + threadIdx.x;
    int task = blockIdx.y;
    if (task == 0) {
        if (idx < HH * 64) {
            int r = idx >> 6, k = idx & 63;
            Bk1[r * 64 + ipos(k)] = __float2bfloat16(kW1[idx]);
        }
    } else if (task == 1) {
        if (idx < HH * 64) {
            int r = idx >> 6, k = idx & 63;
            Bv1[r * 64 + ipos(k)] = __float2bfloat16(k < QD ? vW1[r * QD + k] : 0.f);
        }
    } else if (task == 2) {
        if (idx < HH * HH) {
            int r = idx >> 8, k = idx & 255;
            Bk2[r * HH + ipos(k)] = __float2bfloat16(kW2[idx]);
        }
    } else if (task == 3) {
        if (idx < HH * HH) {
            int r = idx >> 8, k = idx & 255;
            Bv2[r * HH + ipos(k)] = __float2bfloat16(vW2[idx]);
        }
    } else if (task == 4) {
        if (idx < HH * HH) {
            int r = idx >> 8, k = idx & 255;
            Bk2t[r * HH + ipos(k)] = __float2bfloat16(kW2[k * HH + r]);
        }
    } else if (task == 5) {
        if (idx < HH * HH) {
            int r = idx >> 8, k = idx & 255;
            Bv2t[r * HH + ipos(k)] = __float2bfloat16(vW2[k * HH + r]);
        }
    } else if (task == 6) {
        if (idx < 64 * HH) {
            int i = idx >> 8, k = idx & 255;
            float s = 0.f;
            for (int n = 0; n < 64; n++) s += kW1[k * 64 + n] * M[i * 64 + n];
            BMcat[i * 512 + ipos(k)] = __float2bfloat16(s);
        }
    } else if (task == 7) {
        if (idx < 64 * HH) {
            int i = idx >> 8, k = idx & 255;
            float s = 0.f;
            for (int n = 0; n < QD; n++) s += vW1[k * QD + n] * M[i * 64 + n];
            BMcat[i * 512 + 256 + ipos(k)] = __float2bfloat16(s);
        }
    } else {
        if (idx < NLAYERS * 16384) {
            int l = idx / 16384, r = idx % 16384;
            int sel = r / 4096, o = r % 4096;
            float v;
            if (sel == 0)      v = sW1[l * 4096 + o];
            else if (sel == 1) v = sW2[l * 4096 + o];
            else if (sel == 2) v = tW1[l * 4096 + o];
            else               v = tW2[l * 4096 + o];
            fpk[idx] = tf32r(v);
        }
    }
}

// ===========================================================================
// Fully-fused tf32 RealNVP flow (unchanged from round 15)
// ===========================================================================
#define F_Z    0
#define F_CH   4352
#define F_CL   6656
#define F_W1O  8960
#define F_W2O  13568
#define F_HIDO 17792
#define F_B1   26240
#define F_B2   27776
#define F_TOT  28160

__device__ __forceinline__ void flow_stage_w1(uint32_t smb, const float* src, int tid) {
    #pragma unroll
    for (int c = 0; c < 4; c++) {
        int idx = c * 256 + tid;
        int r = idx >> 3, seg = idx & 7;
        cpasync16(smb + (uint32_t)((F_W1O + r * 36 + seg * 4) << 2), src + idx * 4);
    }
}
__device__ __forceinline__ void flow_stage_w2(uint32_t smb, const float* src, int tid) {
    #pragma unroll
    for (int c = 0; c < 4; c++) {
        int idx = c * 256 + tid;
        int r = idx >> 5, seg = idx & 31;
        cpasync16(smb + (uint32_t)((F_W2O + r * 132 + seg * 4) << 2), src + idx * 4);
    }
}

__device__ __forceinline__ void flow_split(float* sm, int tid, int coff) {
    #pragma unroll
    for (int c = 0; c < 8; c++) {
        int idx = c * 256 + tid;
        int r = idx >> 5, cc = idx & 31;
        float y = sm[F_Z + r * 68 + coff + cc];
        float hi = tf32r(y);
        sm[F_CH + r * 36 + cc] = hi;
        sm[F_CL + r * 36 + cc] = tf32r(y - hi);
    }
}

__device__ __forceinline__ void flow_mma1(float* sm, uint32_t smb,
                                          int wm, int wn, int g, int j, int b1off) {
    float acc1[2][4][4];
    #pragma unroll
    for (int mt = 0; mt < 2; mt++)
        #pragma unroll
        for (int nt = 0; nt < 4; nt++)
            #pragma unroll
            for (int i = 0; i < 4; i++) acc1[mt][nt][i] = 0.f;

    uint32_t aH[2], aL[2];
    #pragma unroll
    for (int mt = 0; mt < 2; mt++) {
        int r = wm * 32 + mt * 16 + g;
        aH[mt] = smb + (uint32_t)((F_CH + r * 36 + j) << 2);
        aL[mt] = smb + (uint32_t)((F_CL + r * 36 + j) << 2);
    }
    uint32_t bA[4];
    #pragma unroll
    for (int nt = 0; nt < 4; nt++)
        bA[nt] = smb + (uint32_t)((F_W1O + (wn * 32 + nt * 8 + g) * 36 + j) << 2);

    #pragma unroll
    for (int kc = 0; kc < 4; kc++) {
        const uint32_t ko = (uint32_t)(kc * 32);
        uint32_t ah[2][4], al[2][4];
        #pragma unroll
        for (int mt = 0; mt < 2; mt++) {
            ah[mt][0] = lds32(aH[mt] + ko);
            ah[mt][1] = lds32(aH[mt] + ko + 1152);
            ah[mt][2] = lds32(aH[mt] + ko + 16);
            ah[mt][3] = lds32(aH[mt] + ko + 1168);
            al[mt][0] = lds32(aL[mt] + ko);
            al[mt][1] = lds32(aL[mt] + ko + 1152);
            al[mt][2] = lds32(aL[mt] + ko + 16);
            al[mt][3] = lds32(aL[mt] + ko + 1168);
        }
        #pragma unroll
        for (int nt = 0; nt < 4; nt++) {
            uint32_t b0 = lds32(bA[nt] + ko);
            uint32_t b1 = lds32(bA[nt] + ko + 16);
            #pragma unroll
            for (int mt = 0; mt < 2; mt++) {
                mma_tf32(acc1[mt][nt], ah[mt][0], ah[mt][1], ah[mt][2], ah[mt][3], b0, b1);
                mma_tf32(acc1[mt][nt], al[mt][0], al[mt][1], al[mt][2], al[mt][3], b0, b1);
            }
        }
    }
    #pragma unroll
    for (int mt = 0; mt < 2; mt++) {
        int r0 = wm * 32 + mt * 16 + g;
        #pragma unroll
        for (int nt = 0; nt < 4; nt++) {
            int c0 = wn * 32 + nt * 8 + 2 * j;
            float b0 = sm[b1off + c0], b1f = sm[b1off + c0 + 1];
            sm[F_HIDO + r0 * 132 + c0]           = tf32r(fmaxf(acc1[mt][nt][0] + b0, 0.f));
            sm[F_HIDO + r0 * 132 + c0 + 1]       = tf32r(fmaxf(acc1[mt][nt][1] + b1f, 0.f));
            sm[F_HIDO + (r0 + 8) * 132 + c0]     = tf32r(fmaxf(acc1[mt][nt][2] + b0, 0.f));
            sm[F_HIDO + (r0 + 8) * 132 + c0 + 1] = tf32r(fmaxf(acc1[mt][nt][3] + b1f, 0.f));
        }
    }
}

__device__ __forceinline__ void flow_mma2(uint32_t smb, int wm, int wn, int g, int j,
                                          float res[2][4]) {
    float acc2[2][4];
    #pragma unroll
    for (int mt = 0; mt < 2; mt++)
        #pragma unroll
        for (int i = 0; i < 4; i++) acc2[mt][i] = 0.f;

    uint32_t a2[2];
    #pragma unroll
    for (int mt = 0; mt < 2; mt++)
        a2[mt] = smb + (uint32_t)((F_HIDO + (wm * 32 + mt * 16 + g) * 132 + j) << 2);
    uint32_t b2a = smb + (uint32_t)((F_W2O + (wn * 8 + g) * 132 + j) << 2);

    #pragma unroll 4
    for (int kc = 0; kc < 16; kc++) {
        const uint32_t ko = (uint32_t)(kc * 32);
        uint32_t b0 = lds32(b2a + ko);
        uint32_t b1 = lds32(b2a + ko + 16);
        #pragma unroll
        for (int mt = 0; mt < 2; mt++) {
            uint32_t av0 = lds32(a2[mt] + ko);
            uint32_t av1 = lds32(a2[mt] + ko + 4224);
            uint32_t av2 = lds32(a2[mt] + ko + 16);
            uint32_t av3 = lds32(a2[mt] + ko + 4240);
            mma_tf32(acc2[mt], av0, av1, av2, av3, b0, b1);
        }
    }
    #pragma unroll
    for (int mt = 0; mt < 2; mt++)
        #pragma unroll
        for (int i = 0; i < 4; i++) res[mt][i] = acc2[mt][i];
}

__global__ __launch_bounds__(256, 2)
void flow_fused_k(const float* __restrict__ zin, float* __restrict__ zout,
                  __nv_bfloat16* __restrict__ zkout,
                  const float* __restrict__ fpk,
                  const float* __restrict__ sb1, const float* __restrict__ sb2,
                  const float* __restrict__ tb1, const float* __restrict__ tb2,
                  int inverse) {
    extern __shared__ float sm[];

    const int tid = threadIdx.x, wid = tid >> 5, lane = tid & 31;
    const int g = lane >> 2, j = lane & 3;
    const int wm = wid & 1, wn = wid >> 1;
    const size_t row0 = (size_t)blockIdx.x * 64;
    const uint32_t smb = smem_u32(sm);

    #pragma unroll
    for (int c = 0; c < 4; c++) {
        int idx = c * 256 + tid;
        int r = idx >> 4, seg = idx & 15;
        cpasync16(smb + (uint32_t)((F_Z + r * 68 + seg * 4) << 2),
                  zin + (row0 + r) * DIM + seg * 4);
    }
    const int layer0 = inverse ? NLAYERS - 1 : 0;
    flow_stage_w1(smb, fpk + layer0 * 16384, tid);
    flow_stage_w2(smb, fpk + layer0 * 16384 + 4096, tid);
    cp_commit();

    for (int idx = tid; idx < NLAYERS * HF; idx += 256) {
        sm[F_B1 + idx]       = sb1[idx];
        sm[F_B1 + 768 + idx] = tb1[idx];
    }
    if (tid < NLAYERS * QD) {
        sm[F_B2 + tid]       = sb2[tid];
        sm[F_B2 + 192 + tid] = tb2[tid];
    }

    cp_wait<0>();
    __syncthreads();
    flow_split(sm, tid, (layer0 & 1) ? QD : 0);
    __syncthreads();

    float res_s[2][4], res_t[2][4];

    #pragma unroll 1
    for (int p = 0; p < 2 * NLAYERS; p++) {
        const int lidx  = p >> 1, st = p & 1;
        const int layer = inverse ? NLAYERS - 1 - lidx : lidx;
        const int lnext = inverse ? NLAYERS - 1 - ((p + 1) >> 1) : ((p + 1) >> 1);
        const float* wnext = fpk + lnext * 16384 + ((p + 1) & 1) * 8192;
        const int b1off = F_B1 + st * 768 + layer * HF;

        flow_mma1(sm, smb, wm, wn, g, j, b1off);
        __syncthreads();
        if (p + 1 < 2 * NLAYERS) flow_stage_w1(smb, wnext, tid);
        cp_commit();
        cp_wait<1>();
        __syncthreads();
        float rtmp[2][4];
        flow_mma2(smb, wm, wn, g, j, rtmp);
        #pragma unroll
        for (int mt = 0; mt < 2; mt++)
            #pragma unroll
            for (int i = 0; i < 4; i++) {
                if (st == 0) res_s[mt][i] = rtmp[mt][i];
                else         res_t[mt][i] = rtmp[mt][i];
            }
        __syncthreads();
        if (p + 1 < 2 * NLAYERS) flow_stage_w2(smb, wnext + 4096, tid);
        cp_commit();

        if (st == 1) {
            const int moff = (layer & 1) ? 0 : QD;
            const int c0 = wn * 8 + 2 * j;
            float sb0 = sm[F_B2 + layer * QD + c0];
            float sb1v = sm[F_B2 + layer * QD + c0 + 1];
            float tb0 = sm[F_B2 + 192 + layer * QD + c0];
            float tb1v = sm[F_B2 + 192 + layer * QD + c0 + 1];
            #pragma unroll
            for (int mt = 0; mt < 2; mt++) {
                int r0 = wm * 32 + mt * 16 + g;
                float s0 = tanhf(res_s[mt][0] + sb0);
                float s1 = tanhf(res_s[mt][1] + sb1v);
                float s2 = tanhf(res_s[mt][2] + sb0);
                float s3 = tanhf(res_s[mt][3] + sb1v);
                float t0 = res_t[mt][0] + tb0;
                float t1 = res_t[mt][1] + tb1v;
                float t2 = res_t[mt][2] + tb0;
                float t3 = res_t[mt][3] + tb1v;
                float* z0 = &sm[F_Z + r0 * 68 + moff + c0];
                float* z1 = &sm[F_Z + (r0 + 8) * 68 + moff + c0];
                if (inverse) {
                    z0[0] = (z0[0] - t0) * __expf(-s0);
                    z0[1] = (z0[1] - t1) * __expf(-s1);
                    z1[0] = (z1[0] - t2) * __expf(-s2);
                    z1[1] = (z1[1] - t3) * __expf(-s3);
                } else {
                    z0[0] = fmaf(z0[0], __expf(s0), t0);
                    z0[1] = fmaf(z0[1], __expf(s1), t1);
                    z1[0] = fmaf(z1[0], __expf(s2), t2);
                    z1[1] = fmaf(z1[1], __expf(s3), t3);
                }
            }
        }

        if (p + 1 < 2 * NLAYERS) {
            cp_wait<1>();
            __syncthreads();
            if (st == 1) {
                flow_split(sm, tid, (lnext & 1) ? QD : 0);
                __syncthreads();
            }
        }
    }

    cp_wait<0>();
    __syncthreads();

    #pragma unroll
    for (int c = 0; c < 4; c++) {
        int idx = c * 256 + tid;
        int r = idx >> 4, seg = idx & 15;
        const float* zp = &sm[F_Z + r * 68 + seg * 4];
        float4 v = make_float4(zp[0], zp[1], zp[2], zp[3]);
        *reinterpret_cast<float4*>(zout + (row0 + r) * DIM + seg * 4) = v;
        if (zkout) {
            __nv_bfloat162 a, b;
            a.x = __float2bfloat16(v.x); a.y = __float2bfloat16(v.y);
            b.x = __float2bfloat16(v.z); b.y = __float2bfloat16(v.w);
            int kb = seg * 4;
            *reinterpret_cast<__nv_bfloat162*>(
                zkout + (row0 + r) * DIM + ipos(kb))     = a;
            *reinterpret_cast<__nv_bfloat162*>(
                zkout + (row0 + r) * DIM + ipos(kb + 2)) = b;
        }
    }
}

// ===========================================================================
// Shared GEMM epilogue (interleaved stores; EPI1 sigmoid, EPI2 aux)
// ===========================================================================
template<int EPI, int NT>
__device__ __forceinline__ void gemm_epilogue(
    float acc[2][NT][4], size_t row0, int col0, int wm, int wn, int WN,
    int lane, const float* bia, const float* w3, const __nv_bfloat16* aux,
    char* Cc, int Nld) {
    #pragma unroll
    for (int mt = 0; mt < 2; mt++) {
        const size_t r0 = row0 + wm * 32 + mt * 16 + (lane >> 2);
        const size_t r1 = r0 + 8;
        #pragma unroll
        for (int nt = 0; nt < NT; nt++) {
            const int gc = col0 + wn * WN + nt * 8 + (lane & 3) * 2;
            const int gp = ipos(gc);
            float v0 = acc[mt][nt][0], v1 = acc[mt][nt][1];
            float v2 = acc[mt][nt][2], v3 = acc[mt][nt][3];
            if (EPI == 1) {
                float b0 = bia[gc], b1 = bia[gc + 1];
                float s0 = w3[gc], s1 = w3[gc + 1];
                v0 = s0 / (1.f + __expf(-(v0 + b0)));
                v1 = s1 / (1.f + __expf(-(v1 + b1)));
                v2 = s0 / (1.f + __expf(-(v2 + b0)));
                v3 = s1 / (1.f + __expf(-(v3 + b1)));
            } else if (EPI == 2) {
                __nv_bfloat162 h0 = *reinterpret_cast<const __nv_bfloat162*>(
                    aux + r0 * HH + gp);
                __nv_bfloat162 h1 = *reinterpret_cast<const __nv_bfloat162*>(
                    aux + r1 * HH + gp);
                v0 *= (1.f - __expf(-__bfloat162float(h0.x)));
                v1 *= (1.f - __expf(-__bfloat162float(h0.y)));
                v2 *= (1.f - __expf(-__bfloat162float(h1.x)));
                v3 *= (1.f - __expf(-__bfloat162float(h1.y)));
            }
            __nv_bfloat162 o0; o0.x = __float2bfloat16(v0); o0.y = __float2bfloat16(v1);
            __nv_bfloat162 o1; o1.x = __float2bfloat16(v2); o1.y = __float2bfloat16(v3);
            *reinterpret_cast<__nv_bfloat162*>(
                (__nv_bfloat16*)Cc + r0 * Nld + gp) = o0;
            *reinterpret_cast<__nv_bfloat162*>(
                (__nv_bfloat16*)Cc + r1 * Nld + gp) = o1;
        }
    }
}

// ===========================================================================
// FUSED GEMM1+GEMM2: one 512-thread CTA computes h1 = softplus(zk@W1^T+b1)
// into smem (and gmem for gemm3's aux), then g2 = w3*sigmoid(h1@W2^T+b2)
// with A sourced from smem. 16 warps as 4M x 4N. 1 CTA/SM (172 KB smem).
// ===========================================================================
#define FU_H1  0                  // h1   [128][272] bf16
#define FU_ZK  34816              // zk   [128][80]
#define FU_ST0 45056              // stage buffers [256][80]
#define FU_ST1 65536
#define FU_TOT 86016              // elems -> 172,032 B

__global__ __launch_bounds__(512, 1)
void gemm_fused1(const __nv_bfloat16* __restrict__ zk,
                 const __nv_bfloat16* __restrict__ W1T, const __nv_bfloat16* __restrict__ W1V,
                 const __nv_bfloat16* __restrict__ W2T, const __nv_bfloat16* __restrict__ W2V,
                 const float* __restrict__ b1T, const float* __restrict__ b1V,
                 const float* __restrict__ b2T, const float* __restrict__ b2V,
                 const float* __restrict__ w3T, const float* __restrict__ w3V,
                 __nv_bfloat16* __restrict__ h1T, __nv_bfloat16* __restrict__ h1V,
                 __nv_bfloat16* __restrict__ g2T, __nv_bfloat16* __restrict__ g2V) {
    extern __shared__ __align__(16) __nv_bfloat16 smf[];
    const int tid = threadIdx.x, wid = tid >> 5, lane = tid & 31;
    const int zi = blockIdx.y;
    const __nv_bfloat16* W1 = zi ? W1V : W1T;
    const __nv_bfloat16* W2 = zi ? W2V : W2T;
    const float* b1 = zi ? b1V : b1T;
    const float* b2 = zi ? b2V : b2T;
    const float* w3 = zi ? w3V : w3T;
    __nv_bfloat16* h1 = zi ? h1V : h1T;
    __nv_bfloat16* g2 = zi ? g2V : g2T;
    const size_t row0 = (size_t)blockIdx.x * 128;
    const uint32_t smb = smem_u32(smf);
    const int wm = wid & 3, wn = wid >> 2;     // 4M x 4N
    const int g = lane >> 2, j = lane & 3;

    auto stage_w2 = [&](uint32_t dstE, int c) {   // dstE: element offset
        const int k0 = c * 64;
        #pragma unroll
        for (int t = tid; t < 256 * 8; t += 512) {
            int r = t >> 3, seg = t & 7;
            cpasync16(smb + (uint32_t)((dstE + r * 80 + seg * 8) * 2),
                      W2 + (size_t)r * HH + k0 + seg * 8);
        }
    };

    // ---- group A: zk tile + W1 (into ST0) ----
    #pragma unroll
    for (int t = tid; t < 128 * 8; t += 512) {
        int r = t >> 3, seg = t & 7;
        cpasync16(smb + (uint32_t)((FU_ZK + r * 80 + seg * 8) * 2),
                  zk + (row0 + r) * DIM + seg * 8);
    }
    #pragma unroll
    for (int t = tid; t < 256 * 8; t += 512) {
        int r = t >> 3, seg = t & 7;
        cpasync16(smb + (uint32_t)((FU_ST0 + r * 80 + seg * 8) * 2),
                  W1 + (size_t)r * 64 + seg * 8);
    }
    cp_commit();                  // A
    stage_w2(FU_ST1, 0);
    cp_commit();                  // B (chunk 0 -> ST1)
    cp_wait<1>();                 // A landed
    __syncthreads();

    // ---- phase 1: h1 tile ----
    float acc1[2][8][4];
    #pragma unroll
    for (int mt = 0; mt < 2; mt++)
        #pragma unroll
        for (int nt = 0; nt < 8; nt++)
            #pragma unroll
            for (int i = 0; i < 4; i++) acc1[mt][nt][i] = 0.f;

    {
        uint32_t aB[2];
        #pragma unroll
        for (int mt = 0; mt < 2; mt++)
            aB[mt] = smb + (uint32_t)((FU_ZK + (wm * 32 + mt * 16 + g) * 80) * 2) + j * 8;
        uint32_t bB[8];
        #pragma unroll
        for (int nt = 0; nt < 8; nt++)
            bB[nt] = smb + (uint32_t)((FU_ST0 + (wn * 64 + nt * 8 + g) * 80) * 2) + j * 8;
        constexpr uint32_t R8 = 8 * 80 * 2;
        #pragma unroll
        for (int kc = 0; kc < 4; kc++) {
            const uint32_t kb = (uint32_t)(kc * 32);
            uint32_t a[2][4];
            #pragma unroll
            for (int mt = 0; mt < 2; mt++) {
                lds64(aB[mt] + kb,      a[mt][0], a[mt][2]);
                lds64(aB[mt] + kb + R8, a[mt][1], a[mt][3]);
            }
            uint32_t b[8][2];
            #pragma unroll
            for (int nt = 0; nt < 8; nt++)
                lds64(bB[nt] + kb, b[nt][0], b[nt][1]);
            #pragma unroll
            for (int mt = 0; mt < 2; mt++)
                #pragma unroll
                for (int nt = 0; nt < 8; nt++)
                    mma16816(acc1[mt][nt], a[mt][0], a[mt][1], a[mt][2], a[mt][3],
                             b[nt][0], b[nt][1]);
        }
    }
    __syncthreads();              // ST0 free (all reads done)
    stage_w2(FU_ST0, 1);
    cp_commit();                  // C (chunk 1 -> ST0)

    // ---- epilogue 1: softplus -> h1 smem + gmem ----
    #pragma unroll
    for (int mt = 0; mt < 2; mt++) {
        const int rl0 = wm * 32 + mt * 16 + (lane >> 2);
        const int rl1 = rl0 + 8;
        #pragma unroll
        for (int nt = 0; nt < 8; nt++) {
            const int gc = wn * 64 + nt * 8 + (lane & 3) * 2;
            const int gp = ipos(gc);
            float bb0 = b1[gc], bb1 = b1[gc + 1];
            float v0 = softplus_fast(acc1[mt][nt][0] + bb0);
            float v1 = softplus_fast(acc1[mt][nt][1] + bb1);
            float v2 = softplus_fast(acc1[mt][nt][2] + bb0);
            float v3 = softplus_fast(acc1[mt][nt][3] + bb1);
            __nv_bfloat162 o0; o0.x = __float2bfloat16(v0); o0.y = __float2bfloat16(v1);
            __nv_bfloat162 o1; o1.x = __float2bfloat16(v2); o1.y = __float2bfloat16(v3);
            sts32(smb + (uint32_t)((FU_H1 + rl0 * 272 + gp) * 2),
                  *reinterpret_cast<uint32_t*>(&o0));
            sts32(smb + (uint32_t)((FU_H1 + rl1 * 272 + gp) * 2),
                  *reinterpret_cast<uint32_t*>(&o1));
            *reinterpret_cast<__nv_bfloat162*>(h1 + (row0 + rl0) * HH + gp) = o0;
            *reinterpret_cast<__nv_bfloat162*>(h1 + (row0 + rl1) * HH + gp) = o1;
        }
    }
    __syncthreads();              // h1 smem visible

    // ---- phase 2: g2 = w3*sigmoid(h1 @ W2^T + b2), A from smem ----
    float acc2[2][8][4];
    #pragma unroll
    for (int mt = 0; mt < 2; mt++)
        #pragma unroll
        for (int nt = 0; nt < 8; nt++)
            #pragma unroll
            for (int i = 0; i < 4; i++) acc2[mt][nt][i] = 0.f;

    uint32_t a2B[2];
    #pragma unroll
    for (int mt = 0; mt < 2; mt++)
        a2B[mt] = smb + (uint32_t)((FU_H1 + (wm * 32 + mt * 16 + g) * 272) * 2) + j * 8;
    constexpr uint32_t R8H = 8 * 272 * 2;

    for (int c = 0; c < 4; c++) {
        cp_wait<1>();             // chunk c landed
        __syncthreads();
        const uint32_t stE = (c & 1) ? FU_ST0 : FU_ST1;
        const uint32_t coff = (uint32_t)(c * 128);   // c*64 elems in bytes
        uint32_t bB[8];
        #pragma unroll
        for (int nt = 0; nt < 8; nt++)
            bB[nt] = smb + (uint32_t)((stE + (wn * 64 + nt * 8 + g) * 80) * 2) + j * 8;
        #pragma unroll
        for (int kc = 0; kc < 4; kc++) {
            const uint32_t kb = (uint32_t)(kc * 32);
            uint32_t a[2][4];
            #pragma unroll
            for (int mt = 0; mt < 2; mt++) {
                lds64(a2B[mt] + coff + kb,       a[mt][0], a[mt][2]);
                lds64(a2B[mt] + coff + kb + R8H, a[mt][1], a[mt][3]);
            }
            uint32_t b[8][2];
            #pragma unroll
            for (int nt = 0; nt < 8; nt++)
                lds64(bB[nt] + kb, b[nt][0], b[nt][1]);
            #pragma unroll
            for (int mt = 0; mt < 2; mt++)
                #pragma unroll
                for (int nt = 0; nt < 8; nt++)
                    mma16816(acc2[mt][nt], a[mt][0], a[mt][1], a[mt][2], a[mt][3],
                             b[nt][0], b[nt][1]);
        }
        __syncthreads();
        if (c + 2 < 4) stage_w2(stE, c + 2);   // refill just-freed buffer
        cp_commit();
    }

    gemm_epilogue<1, 8>(acc2, row0, 0, wm, wn, 64, lane, b2, w3, 0, (char*)g2, HH);
}

// ===========================================================================
// cp.async 2-stage pipelined warp-MMA GEMM (K = 256, BK = 64, LDE = 80)
// (used for GEMM3 only)
// ===========================================================================
template<int K, int BN, int EPI>
__global__ __launch_bounds__(256, 2)
void gemm_pipe(const __nv_bfloat16* __restrict__ A0, const __nv_bfloat16* __restrict__ A1,
               const __nv_bfloat16* __restrict__ B0, const __nv_bfloat16* __restrict__ B1,
               const float* __restrict__ bias0, const float* __restrict__ bias1,
               const float* __restrict__ w30,  const float* __restrict__ w31,
               const __nv_bfloat16* __restrict__ aux0, const __nv_bfloat16* __restrict__ aux1,
               void* __restrict__ C0, void* __restrict__ C1, int Nld) {
    constexpr int BK   = 64;
    constexpr int LDE  = BK + 16;
    constexpr int NSTG = 2;
    constexpr int NCH  = K / BK;
    constexpr int STGE = (128 + BN) * LDE;
    extern __shared__ __align__(16) __nv_bfloat16 smp[];

    const int tid = threadIdx.x, wid = tid >> 5, lane = tid & 31;
    const int zi = blockIdx.z;
    const __nv_bfloat16* A   = zi ? A1 : A0;
    const __nv_bfloat16* Bw  = zi ? B1 : B0;
    const float* bia         = zi ? bias1 : bias0;
    const float* w3          = zi ? w31 : w30;
    const __nv_bfloat16* aux = zi ? aux1 : aux0;
    char* Cc                 = (char*)(zi ? C1 : C0);

    const size_t row0 = (size_t)blockIdx.x * 128;
    const int    col0 = blockIdx.y * BN;
    const uint32_t sm0 = smem_u32(smp);

    auto load_chunk = [&](int s, int c) {
        const uint32_t dstS = sm0 + (uint32_t)(s * STGE * 2);
        const int k0 = c * BK;
        #pragma unroll
        for (int t = tid; t < (128 + BN) * 8; t += 256) {
            int r = t >> 3, seg = t & 7;
            if (r < 128) {
                cpasync16(dstS + (uint32_t)((r * LDE + seg * 8) * 2),
                          A + (row0 + r) * K + k0 + seg * 8);
            } else {
                int rb = r - 128;
                cpasync16(dstS + (uint32_t)(((128 + rb) * LDE + seg * 8) * 2),
                          Bw + (size_t)(col0 + rb) * K + k0 + seg * 8);
            }
        }
    };

    const int wm = wid & 3;
    const int wn = wid >> 2;
    constexpr int WN = BN / 2;
    constexpr int NT = WN / 8;
    const int g = lane >> 2;
    const int j = lane & 3;

    float acc[2][NT][4];
    #pragma unroll
    for (int mt = 0; mt < 2; mt++)
        #pragma unroll
        for (int nt = 0; nt < NT; nt++)
            #pragma unroll
            for (int i = 0; i < 4; i++) acc[mt][nt][i] = 0.f;

    uint32_t aBase[2];
    #pragma unroll
    for (int mt = 0; mt < 2; mt++)
        aBase[mt] = sm0 + (uint32_t)((wm * 32 + mt * 16 + g) * LDE * 2 + j * 8);
    uint32_t bBase[NT];
    #pragma unroll
    for (int nt = 0; nt < NT; nt++)
        bBase[nt] = sm0 + (uint32_t)((128 + wn * WN + nt * 8 + g) * LDE * 2 + j * 8);
    constexpr uint32_t ROW8 = (uint32_t)(8 * LDE * 2);

    load_chunk(0, 0); cp_commit();
    load_chunk(1, 1); cp_commit();

    for (int c = 0; c < NCH; c++) {
        cp_wait<1>();
        __syncthreads();
        const uint32_t soff = (uint32_t)((c % NSTG) * STGE * 2);
        #pragma unroll
        for (int kc = 0; kc < BK / 16; kc++) {
            const uint32_t kb = soff + (uint32_t)(kc * 32);
            uint32_t a[2][4];
            #pragma unroll
            for (int mt = 0; mt < 2; mt++) {
                lds64(aBase[mt] + kb,        a[mt][0], a[mt][2]);
                lds64(aBase[mt] + kb + ROW8, a[mt][1], a[mt][3]);
            }
            uint32_t b[NT][2];
            #pragma unroll
            for (int nt = 0; nt < NT; nt++)
                lds64(bBase[nt] + kb, b[nt][0], b[nt][1]);
            #pragma unroll
            for (int mt = 0; mt < 2; mt++)
                #pragma unroll
                for (int nt = 0; nt < NT; nt++)
                    mma16816(acc[mt][nt], a[mt][0], a[mt][1], a[mt][2], a[mt][3],
                             b[nt][0], b[nt][1]);
        }
        __syncthreads();
        if (c + 2 < NCH) load_chunk((c + 2) % NSTG, c + 2);
        cp_commit();
    }

    gemm_epilogue<EPI, NT>(acc, row0, col0, wm, wn, WN, lane, bia, w3, aux, Cc, Nld);
}

// ===========================================================================
// Fused final GEMM (K=512: [g1T | g1V] @ BMcat^T) + RK4 epilogue.
// ===========================================================================
__global__ __launch_bounds__(256, 2)
void gemm_rk4(const __nv_bfloat16* __restrict__ g1T, const __nv_bfloat16* __restrict__ g1V,
              const __nv_bfloat16* __restrict__ Bw,
              const float* __restrict__ u, const float* __restrict__ Bc,
              const float* __restrict__ zg, float* __restrict__ accg,
              __nv_bfloat16* __restrict__ zk, float* __restrict__ outg, int stage) {
    constexpr int BK   = 64;
    constexpr int LDE  = BK + 16;
    constexpr int NSTG = 3;
    constexpr int NCH  = 8;
    constexpr int BN   = 64;
    constexpr int STGE = (128 + BN) * LDE;
    extern __shared__ __align__(16) __nv_bfloat16 smp[];

    const int tid = threadIdx.x, wid = tid >> 5, lane = tid & 31;
    const size_t row0 = (size_t)blockIdx.x * 128;
    const uint32_t sm0 = smem_u32(smp);

    auto load_chunk = [&](int s, int c) {
        const uint32_t dstS = sm0 + (uint32_t)(s * STGE * 2);
        const __nv_bfloat16* A = (c < 4) ? g1T : g1V;
        const int k0 = (c & 3) * BK;
        #pragma unroll
        for (int t = tid; t < (128 + BN) * 8; t += 256) {
            int r = t >> 3, seg = t & 7;
            if (r < 128) {
                cpasync16(dstS + (uint32_t)((r * LDE + seg * 8) * 2),
                          A + (row0 + r) * HH + k0 + seg * 8);
            } else {
                int rb = r - 128;
                cpasync16(dstS + (uint32_t)(((128 + rb) * LDE + seg * 8) * 2),
                          Bw + (size_t)rb * 512 + c * BK + seg * 8);
            }
        }
    };

    const int wm = wid & 3;
    const int wn = wid >> 2;
    constexpr int WN = BN / 2;
    constexpr int NT = WN / 8;
    const int g = lane >> 2;
    const int j = lane & 3;

    float acc[2][NT][4];
    #pragma unroll
    for (int mt = 0; mt < 2; mt++)
        #pragma unroll
        for (int nt = 0; nt < NT; nt++)
            #pragma unroll
            for (int i = 0; i < 4; i++) acc[mt][nt][i] = 0.f;

    uint32_t aBase[2];
    #pragma unroll
    for (int mt = 0; mt < 2; mt++)
        aBase[mt] = sm0 + (uint32_t)((wm * 32 + mt * 16 + g) * LDE * 2 + j * 8);
    uint32_t bBase[NT];
    #pragma unroll
    for (int nt = 0; nt < NT; nt++)
        bBase[nt] = sm0 + (uint32_t)((128 + wn * WN + nt * 8 + g) * LDE * 2 + j * 8);
    constexpr uint32_t ROW8 = (uint32_t)(8 * LDE * 2);

    load_chunk(0, 0); cp_commit();
    load_chunk(1, 1); cp_commit();

    for (int c = 0; c < NCH; c++) {
        cp_wait<1>();
        __syncthreads();
        const uint32_t soff = (uint32_t)((c % NSTG) * STGE * 2);
        #pragma unroll
        for (int kc = 0; kc < BK / 16; kc++) {
            const uint32_t kb = soff + (uint32_t)(kc * 32);
            uint32_t a[2][4];
            #pragma unroll
            for (int mt = 0; mt < 2; mt++) {
                lds64(aBase[mt] + kb,        a[mt][0], a[mt][2]);
                lds64(aBase[mt] + kb + ROW8, a[mt][1], a[mt][3]);
            }
            uint32_t b[NT][2];
            #pragma unroll
            for (int nt = 0; nt < NT; nt++)
                lds64(bBase[nt] + kb, b[nt][0], b[nt][1]);
            #pragma unroll
            for (int mt = 0; mt < 2; mt++)
                #pragma unroll
                for (int nt = 0; nt < NT; nt++)
                    mma16816(acc[mt][nt], a[mt][0], a[mt][1], a[mt][2], a[mt][3],
                             b[nt][0], b[nt][1]);
        }
        __syncthreads();
        if (c + 2 < NCH) load_chunk((c + 2) % NSTG, c + 2);
        cp_commit();
    }

    const float wgt = (stage == 1 || stage == 2) ? 2.f : 1.f;
    const float cn  = (stage == 2) ? DTC : 0.5f * DTC;
    #pragma unroll
    for (int mt = 0; mt < 2; mt++) {
        const size_t r0 = row0 + wm * 32 + mt * 16 + (lane >> 2);
        const size_t r1 = r0 + 8;
        const float u0 = u[r0], u1 = u[r1];
        #pragma unroll
        for (int nt = 0; nt < NT; nt++) {
            const int gc = wn * WN + nt * 8 + (lane & 3) * 2;
            float dz0 = acc[mt][nt][0], dz1 = acc[mt][nt][1];
            float dz2 = acc[mt][nt][2], dz3 = acc[mt][nt][3];
            if (gc >= QD) {
                float bc0 = Bc[gc - QD], bc1 = Bc[gc - QD + 1];
                dz0 = fmaf(u0, bc0, dz0); dz1 = fmaf(u0, bc1, dz1);
                dz2 = fmaf(u1, bc0, dz2); dz3 = fmaf(u1, bc1, dz3);
            }
            const size_t i0 = r0 * DIM + gc, i1 = r1 * DIM + gc;
            float2 ap0 = make_float2(0.f, 0.f), ap1 = make_float2(0.f, 0.f);
            if (stage != 0) {
                ap0 = *reinterpret_cast<float2*>(accg + i0);
                ap1 = *reinterpret_cast<float2*>(accg + i1);
            }
            float a0 = fmaf(wgt, dz0, ap0.x), a1 = fmaf(wgt, dz1, ap0.y);
            float a2 = fmaf(wgt, dz2, ap1.x), a3 = fmaf(wgt, dz3, ap1.y);
            *reinterpret_cast<float2*>(accg + i0) = make_float2(a0, a1);
            *reinterpret_cast<float2*>(accg + i1) = make_float2(a2, a3);
            float2 z0 = *reinterpret_cast<const float2*>(zg + i0);
            float2 z1 = *reinterpret_cast<const float2*>(zg + i1);
            if (stage < 3) {
                const int gp = ipos(gc);
                __nv_bfloat162 o0, o1;
                o0.x = __float2bfloat16(fmaf(cn, dz0, z0.x));
                o0.y = __float2bfloat16(fmaf(cn, dz1, z0.y));
                o1.x = __float2bfloat16(fmaf(cn, dz2, z1.x));
                o1.y = __float2bfloat16(fmaf(cn, dz3, z1.y));
                *reinterpret_cast<__nv_bfloat162*>(zk + r0 * DIM + gp) = o0;
                *reinterpret_cast<__nv_bfloat162*>(zk + r1 * DIM + gp) = o1;
            } else {
                *reinterpret_cast<float2*>(outg + i0) =
                    make_float2(fmaf(DTC / 6.f, a0, z0.x), fmaf(DTC / 6.f, a1, z0.y));
                *reinterpret_cast<float2*>(outg + i1) =
                    make_float2(fmaf(DTC / 6.f, a2, z1.x), fmaf(DTC / 6.f, a3, z1.y));
            }
        }
    }
}

// ===========================================================================
// Host orchestration
// ===========================================================================
extern "C" void kernel_launch(void* const* d_in, const int* in_sizes, int n_in,
                              void* d_out, int out_size) {
    const float* h    = (const float*)d_in[0];
    const float* u    = (const float*)d_in[1];
    const float* sW1  = (const float*)d_in[2];
    const float* sb1  = (const float*)d_in[3];
    const float* sW2  = (const float*)d_in[4];
    const float* sb2  = (const float*)d_in[5];
    const float* tW1  = (const float*)d_in[6];
    const float* tb1  = (const float*)d_in[7];
    const float* tW2  = (const float*)d_in[8];
    const float* tb2  = (const float*)d_in[9];
    const float* kW1  = (const float*)d_in[10];
    const float* kb1  = (const float*)d_in[11];
    const float* kW2  = (const float*)d_in[12];
    const float* kb2  = (const float*)d_in[13];
    const float* kW3  = (const float*)d_in[14];
    const float* vW1  = (const float*)d_in[16];
    const float* vb1  = (const float*)d_in[17];
    const float* vW2  = (const float*)d_in[18];
    const float* vb2  = (const float*)d_in[19];
    const float* vW3  = (const float*)d_in[20];
    const float* A    = (const float*)d_in[22];
    const float* Lp   = (const float*)d_in[23];
    const float* Bc   = (const float*)d_in[24];
    float* out = (float*)d_out;

    float *z, *acc, *Mp, *fpk;
    __nv_bfloat16 *zk, *h1T, *h1V, *g2T, *g2V, *g1T, *g1V;
    __nv_bfloat16 *Bk1, *Bv1, *Bk2, *Bv2, *Bk2t, *Bv2t, *BMcat;
    cudaGetSymbolAddress((void**)&z,     g_z);
    cudaGetSymbolAddress((void**)&acc,   g_acc);
    cudaGetSymbolAddress((void**)&zk,    g_zk);
    cudaGetSymbolAddress((void**)&h1T,   g_h1T);
    cudaGetSymbolAddress((void**)&h1V,   g_h1V);
    cudaGetSymbolAddress((void**)&g2T,   g_g2T);
    cudaGetSymbolAddress((void**)&g2V,   g_g2V);
    cudaGetSymbolAddress((void**)&g1T,   g_g1T);
    cudaGetSymbolAddress((void**)&g1V,   g_g1V);
    cudaGetSymbolAddress((void**)&Bk1,   g_Bk1);
    cudaGetSymbolAddress((void**)&Bv1,   g_Bv1);
    cudaGetSymbolAddress((void**)&Bk2,   g_Bk2);
    cudaGetSymbolAddress((void**)&Bv2,   g_Bv2);
    cudaGetSymbolAddress((void**)&Bk2t,  g_Bk2t);
    cudaGetSymbolAddress((void**)&Bv2t,  g_Bv2t);
    cudaGetSymbolAddress((void**)&BMcat, g_BMcat);
    cudaGetSymbolAddress((void**)&Mp,    g_M);
    cudaGetSymbolAddress((void**)&fpk,   g_fpk);

    const int SMP128 = 2 * (128 + 128) * 80 * 2;       //  81,920
    const int SMP64  = 3 * (128 + 64)  * 80 * 2;       //  92,160
    const int SMF    = F_TOT * 4;                      // 112,640
    const int SMFU   = FU_TOT * 2;                     // 172,032
    cudaFuncSetAttribute(gemm_fused1,
                         cudaFuncAttributeMaxDynamicSharedMemorySize, SMFU);
    cudaFuncSetAttribute(gemm_pipe<256, 128, 2>,
                         cudaFuncAttributeMaxDynamicSharedMemorySize, SMP128);
    cudaFuncSetAttribute(gemm_rk4,
                         cudaFuncAttributeMaxDynamicSharedMemorySize, SMP64);
    cudaFuncSetAttribute(flow_fused_k,
                         cudaFuncAttributeMaxDynamicSharedMemorySize, SMF);

    // ---- prep: 2 launches ----
    build_M_k<<<1, 256>>>(A, Lp, Mp);
    prep_pack_k<<<dim3(384, 9), 256>>>(kW1, vW1, kW2, vW2, Mp,
                                       sW1, sW2, tW1, tW2,
                                       Bk1, Bv1, Bk2, Bv2, Bk2t, Bv2t,
                                       BMcat, fpk);

    // ---- s = flow_fwd(h) ----
    flow_fused_k<<<BATCH / 64, 256, SMF>>>(h, z, zk, fpk, sb1, sb2, tb1, tb2, 0);

    // ---- RK4 stages ----
    dim3 gFu(BATCH / 128, 2);
    dim3 gBig(BATCH / 128, 2, 2);
    for (int st = 0; st < 4; st++) {
        gemm_fused1<<<gFu, 512, SMFU>>>(
            zk, Bk1, Bv1, Bk2, Bv2, kb1, vb1, kb2, vb2, kW3, vW3,
            h1T, h1V, g2T, g2V);
        gemm_pipe<256, 128, 2><<<gBig, 256, SMP128>>>(
            g2T, g2V, Bk2t, Bv2t, 0, 0, 0, 0, h1T, h1V, g1T, g1V, HH);
        gemm_rk4<<<BATCH / 128, 256, SMP64>>>(
            g1T, g1V, BMcat, u, Bc, z, acc, zk, out, st);
    }

    // ---- h_next = flow_inv(z_next) in place on out ----
    flow_fused_k<<<BATCH / 64, 256, SMF>>>(out, out, (__nv_bfloat16*)0,
                                           fpk, sb1, sb2, tb1, tb2, 1);
}

// round 17
// speedup vs baseline: 1.0405x; 1.0405x over previous
#include <cuda_runtime.h>
#include <cuda_bf16.h>
#include <math.h>
#include <cstdint>

#define BATCH   131072
#define DIM     64
#define QD      32
#define NLAYERS 6
#define HF      128
#define HH      256
#define DTC     0.05f

// ===========================================================================
// Pair-interleaved K layout: fragment pairs adjacent -> one LDS.64.
// ===========================================================================
__host__ __device__ __forceinline__ int ipos(int k) {
    return (k & ~15) | (((k >> 1) & 3) << 2) | ((k & 8) >> 2) | (k & 1);
}

// ===========================================================================
// Scratch (static __device__ arrays)
// ===========================================================================
__device__ __align__(16) float g_z   [BATCH * DIM];
__device__ __align__(16) float g_acc [BATCH * DIM];
__device__ __align__(16) __nv_bfloat16 g_zk [BATCH * DIM];       // k-interleaved
__device__ __align__(16) __nv_bfloat16 g_h1T[BATCH * HH];        // k-interleaved
__device__ __align__(16) __nv_bfloat16 g_h1V[BATCH * HH];
__device__ __align__(16) __nv_bfloat16 g_g2T[BATCH * HH];
__device__ __align__(16) __nv_bfloat16 g_g2V[BATCH * HH];
__device__ __align__(16) __nv_bfloat16 g_g1T[BATCH * HH];
__device__ __align__(16) __nv_bfloat16 g_g1V[BATCH * HH];
// bf16 weight images, row-major [N][K], K pair-interleaved
__device__ __align__(16) __nv_bfloat16 g_Bk1  [HH * 64];
__device__ __align__(16) __nv_bfloat16 g_Bv1  [HH * 64];
__device__ __align__(16) __nv_bfloat16 g_Bk2  [HH * HH];
__device__ __align__(16) __nv_bfloat16 g_Bv2  [HH * HH];
__device__ __align__(16) __nv_bfloat16 g_Bk2t [HH * HH];
__device__ __align__(16) __nv_bfloat16 g_Bv2t [HH * HH];
__device__ __align__(16) __nv_bfloat16 g_BMcat[64 * 512];
__device__ float g_M[DIM * DIM];
// flow weights, tf32-rounded (natural layout)
__device__ __align__(16) float g_fpk[NLAYERS * 16384];

__device__ __forceinline__ float softplusf(float x) {
    return fmaxf(x, 0.f) + log1pf(expf(-fabsf(x)));
}
__device__ __forceinline__ float softplus_fast(float x) {
    return fmaxf(x, 0.f) + __logf(1.f + __expf(-fabsf(x)));
}

__device__ __forceinline__ uint32_t smem_u32(const void* p) {
    uint32_t a;
    asm("{ .reg .u64 t; cvta.to.shared.u64 t, %1; cvt.u32.u64 %0, t; }"
        : "=r"(a) : "l"(p));
    return a;
}

// VOLATILE shared loads (no CSE across barriers)
__device__ __forceinline__ uint32_t lds32(uint32_t addr) {
    uint32_t v;
    asm volatile("ld.shared.b32 %0, [%1];" : "=r"(v) : "r"(addr));
    return v;
}
__device__ __forceinline__ void lds64(uint32_t addr, uint32_t& x, uint32_t& y) {
    asm volatile("ld.shared.v2.b32 {%0, %1}, [%2];" : "=r"(x), "=r"(y) : "r"(addr));
}

__device__ __forceinline__ float tf32r(float x) {
    uint32_t u;
    asm("cvt.rna.tf32.f32 %0, %1;" : "=r"(u) : "f"(x));
    return __uint_as_float(u);
}

__device__ __forceinline__ void cpasync16(uint32_t dst, const void* src) {
    asm volatile("cp.async.cg.shared.global [%0], [%1], 16;"
                 :: "r"(dst), "l"(src));
}
__device__ __forceinline__ void cp_commit() {
    asm volatile("cp.async.commit_group;");
}
template<int N>
__device__ __forceinline__ void cp_wait() {
    asm volatile("cp.async.wait_group %0;" :: "n"(N));
}

__device__ __forceinline__ void mma16816(float* c, uint32_t a0, uint32_t a1,
                                         uint32_t a2, uint32_t a3,
                                         uint32_t b0, uint32_t b1) {
    asm volatile(
        "mma.sync.aligned.m16n8k16.row.col.f32.bf16.bf16.f32 "
        "{%0,%1,%2,%3},{%4,%5,%6,%7},{%8,%9},{%0,%1,%2,%3};"
        : "+f"(c[0]), "+f"(c[1]), "+f"(c[2]), "+f"(c[3])
        : "r"(a0), "r"(a1), "r"(a2), "r"(a3), "r"(b0), "r"(b1));
}

__device__ __forceinline__ void mma_tf32(float* c, uint32_t a0, uint32_t a1,
                                         uint32_t a2, uint32_t a3,
                                         uint32_t b0, uint32_t b1) {
    asm volatile(
        "mma.sync.aligned.m16n8k8.row.col.f32.tf32.tf32.f32 "
        "{%0,%1,%2,%3},{%4,%5,%6,%7},{%8,%9},{%0,%1,%2,%3};"
        : "+f"(c[0]), "+f"(c[1]), "+f"(c[2]), "+f"(c[3])
        : "r"(a0), "r"(a1), "r"(a2), "r"(a3), "r"(b0), "r"(b1));
}

// ===========================================================================
// Prep kernels
// ===========================================================================
__global__ void build_M_k(const float* __restrict__ A, const float* __restrict__ Lp,
                          float* __restrict__ M) {
    __shared__ float L[DIM * DIM];
    int t = threadIdx.x;
    for (int idx = t; idx < DIM * DIM; idx += 256) {
        int i = idx >> 6, j = idx & 63;
        float v;
        if (i > j)       v = Lp[idx];
        else if (i == j) v = softplusf(Lp[idx]);
        else             v = 0.f;
        L[idx] = v;
    }
    __syncthreads();
    for (int idx = t; idx < DIM * DIM; idx += 256) {
        int i = idx >> 6, j = idx & 63;
        float s = 0.f;
        #pragma unroll 8
        for (int k = 0; k < DIM; k++) s += L[i * DIM + k] * L[j * DIM + k];
        M[idx] = A[i * DIM + j] - A[j * DIM + i] - s;
    }
}

__global__ void prep_pack_k(const float* __restrict__ kW1, const float* __restrict__ vW1,
                            const float* __restrict__ kW2, const float* __restrict__ vW2,
                            const float* __restrict__ M,
                            const float* __restrict__ sW1, const float* __restrict__ sW2,
                            const float* __restrict__ tW1, const float* __restrict__ tW2,
                            __nv_bfloat16* __restrict__ Bk1, __nv_bfloat16* __restrict__ Bv1,
                            __nv_bfloat16* __restrict__ Bk2, __nv_bfloat16* __restrict__ Bv2,
                            __nv_bfloat16* __restrict__ Bk2t, __nv_bfloat16* __restrict__ Bv2t,
                            __nv_bfloat16* __restrict__ BMcat,
                            float* __restrict__ fpk) {
    int idx = blockIdx.x * 256 + threadIdx.x;
    int task = blockIdx.y;
    if (task == 0) {
        if (idx < HH * 64) {
            int r = idx >> 6, k = idx & 63;
            Bk1[r * 64 + ipos(k)] = __float2bfloat16(kW1[idx]);
        }
    } else if (task == 1) {
        if (idx < HH * 64) {
            int r = idx >> 6, k = idx & 63;
            Bv1[r * 64 + ipos(k)] = __float2bfloat16(k < QD ? vW1[r * QD + k] : 0.f);
        }
    } else if (task == 2) {
        if (idx < HH * HH) {
            int r = idx >> 8, k = idx & 255;
            Bk2[r * HH + ipos(k)] = __float2bfloat16(kW2[idx]);
        }
    } else if (task == 3) {
        if (idx < HH * HH) {
            int r = idx >> 8, k = idx & 255;
            Bv2[r * HH + ipos(k)] = __float2bfloat16(vW2[idx]);
        }
    } else if (task == 4) {
        if (idx < HH * HH) {
            int r = idx >> 8, k = idx & 255;
            Bk2t[r * HH + ipos(k)] = __float2bfloat16(kW2[k * HH + r]);
        }
    } else if (task == 5) {
        if (idx < HH * HH) {
            int r = idx >> 8, k = idx & 255;
            Bv2t[r * HH + ipos(k)] = __float2bfloat16(vW2[k * HH + r]);
        }
    } else if (task == 6) {
        if (idx < 64 * HH) {
            int i = idx >> 8, k = idx & 255;
            float s = 0.f;
            for (int n = 0; n < 64; n++) s += kW1[k * 64 + n] * M[i * 64 + n];
            BMcat[i * 512 + ipos(k)] = __float2bfloat16(s);
        }
    } else if (task == 7) {
        if (idx < 64 * HH) {
            int i = idx >> 8, k = idx & 255;
            float s = 0.f;
            for (int n = 0; n < QD; n++) s += vW1[k * QD + n] * M[i * 64 + n];
            BMcat[i * 512 + 256 + ipos(k)] = __float2bfloat16(s);
        }
    } else {
        if (idx < NLAYERS * 16384) {
            int l = idx / 16384, r = idx % 16384;
            int sel = r / 4096, o = r % 4096;
            float v;
            if (sel == 0)      v = sW1[l * 4096 + o];
            else if (sel == 1) v = sW2[l * 4096 + o];
            else if (sel == 2) v = tW1[l * 4096 + o];
            else               v = tW2[l * 4096 + o];
            fpk[idx] = tf32r(v);
        }
    }
}

// ===========================================================================
// Fully-fused tf32 RealNVP flow (proven rounds 13-15, unchanged)
// ===========================================================================
#define F_Z    0
#define F_CH   4352
#define F_CL   6656
#define F_W1O  8960
#define F_W2O  13568
#define F_HIDO 17792
#define F_B1   26240
#define F_B2   27776
#define F_TOT  28160

__device__ __forceinline__ void flow_stage_w1(uint32_t smb, const float* src, int tid) {
    #pragma unroll
    for (int c = 0; c < 4; c++) {
        int idx = c * 256 + tid;
        int r = idx >> 3, seg = idx & 7;
        cpasync16(smb + (uint32_t)((F_W1O + r * 36 + seg * 4) << 2), src + idx * 4);
    }
}
__device__ __forceinline__ void flow_stage_w2(uint32_t smb, const float* src, int tid) {
    #pragma unroll
    for (int c = 0; c < 4; c++) {
        int idx = c * 256 + tid;
        int r = idx >> 5, seg = idx & 31;
        cpasync16(smb + (uint32_t)((F_W2O + r * 132 + seg * 4) << 2), src + idx * 4);
    }
}

__device__ __forceinline__ void flow_split(float* sm, int tid, int coff) {
    #pragma unroll
    for (int c = 0; c < 8; c++) {
        int idx = c * 256 + tid;
        int r = idx >> 5, cc = idx & 31;
        float y = sm[F_Z + r * 68 + coff + cc];
        float hi = tf32r(y);
        sm[F_CH + r * 36 + cc] = hi;
        sm[F_CL + r * 36 + cc] = tf32r(y - hi);
    }
}

__device__ __forceinline__ void flow_mma1(float* sm, uint32_t smb,
                                          int wm, int wn, int g, int j, int b1off) {
    float acc1[2][4][4];
    #pragma unroll
    for (int mt = 0; mt < 2; mt++)
        #pragma unroll
        for (int nt = 0; nt < 4; nt++)
            #pragma unroll
            for (int i = 0; i < 4; i++) acc1[mt][nt][i] = 0.f;

    uint32_t aH[2], aL[2];
    #pragma unroll
    for (int mt = 0; mt < 2; mt++) {
        int r = wm * 32 + mt * 16 + g;
        aH[mt] = smb + (uint32_t)((F_CH + r * 36 + j) << 2);
        aL[mt] = smb + (uint32_t)((F_CL + r * 36 + j) << 2);
    }
    uint32_t bA[4];
    #pragma unroll
    for (int nt = 0; nt < 4; nt++)
        bA[nt] = smb + (uint32_t)((F_W1O + (wn * 32 + nt * 8 + g) * 36 + j) << 2);

    #pragma unroll
    for (int kc = 0; kc < 4; kc++) {
        const uint32_t ko = (uint32_t)(kc * 32);
        uint32_t ah[2][4], al[2][4];
        #pragma unroll
        for (int mt = 0; mt < 2; mt++) {
            ah[mt][0] = lds32(aH[mt] + ko);
            ah[mt][1] = lds32(aH[mt] + ko + 1152);
            ah[mt][2] = lds32(aH[mt] + ko + 16);
            ah[mt][3] = lds32(aH[mt] + ko + 1168);
            al[mt][0] = lds32(aL[mt] + ko);
            al[mt][1] = lds32(aL[mt] + ko + 1152);
            al[mt][2] = lds32(aL[mt] + ko + 16);
            al[mt][3] = lds32(aL[mt] + ko + 1168);
        }
        #pragma unroll
        for (int nt = 0; nt < 4; nt++) {
            uint32_t b0 = lds32(bA[nt] + ko);
            uint32_t b1 = lds32(bA[nt] + ko + 16);
            #pragma unroll
            for (int mt = 0; mt < 2; mt++) {
                mma_tf32(acc1[mt][nt], ah[mt][0], ah[mt][1], ah[mt][2], ah[mt][3], b0, b1);
                mma_tf32(acc1[mt][nt], al[mt][0], al[mt][1], al[mt][2], al[mt][3], b0, b1);
            }
        }
    }
    #pragma unroll
    for (int mt = 0; mt < 2; mt++) {
        int r0 = wm * 32 + mt * 16 + g;
        #pragma unroll
        for (int nt = 0; nt < 4; nt++) {
            int c0 = wn * 32 + nt * 8 + 2 * j;
            float b0 = sm[b1off + c0], b1f = sm[b1off + c0 + 1];
            sm[F_HIDO + r0 * 132 + c0]           = tf32r(fmaxf(acc1[mt][nt][0] + b0, 0.f));
            sm[F_HIDO + r0 * 132 + c0 + 1]       = tf32r(fmaxf(acc1[mt][nt][1] + b1f, 0.f));
            sm[F_HIDO + (r0 + 8) * 132 + c0]     = tf32r(fmaxf(acc1[mt][nt][2] + b0, 0.f));
            sm[F_HIDO + (r0 + 8) * 132 + c0 + 1] = tf32r(fmaxf(acc1[mt][nt][3] + b1f, 0.f));
        }
    }
}

__device__ __forceinline__ void flow_mma2(uint32_t smb, int wm, int wn, int g, int j,
                                          float res[2][4]) {
    float acc2[2][4];
    #pragma unroll
    for (int mt = 0; mt < 2; mt++)
        #pragma unroll
        for (int i = 0; i < 4; i++) acc2[mt][i] = 0.f;

    uint32_t a2[2];
    #pragma unroll
    for (int mt = 0; mt < 2; mt++)
        a2[mt] = smb + (uint32_t)((F_HIDO + (wm * 32 + mt * 16 + g) * 132 + j) << 2);
    uint32_t b2a = smb + (uint32_t)((F_W2O + (wn * 8 + g) * 132 + j) << 2);

    #pragma unroll 4
    for (int kc = 0; kc < 16; kc++) {
        const uint32_t ko = (uint32_t)(kc * 32);
        uint32_t b0 = lds32(b2a + ko);
        uint32_t b1 = lds32(b2a + ko + 16);
        #pragma unroll
        for (int mt = 0; mt < 2; mt++) {
            uint32_t av0 = lds32(a2[mt] + ko);
            uint32_t av1 = lds32(a2[mt] + ko + 4224);
            uint32_t av2 = lds32(a2[mt] + ko + 16);
            uint32_t av3 = lds32(a2[mt] + ko + 4240);
            mma_tf32(acc2[mt], av0, av1, av2, av3, b0, b1);
        }
    }
    #pragma unroll
    for (int mt = 0; mt < 2; mt++)
        #pragma unroll
        for (int i = 0; i < 4; i++) res[mt][i] = acc2[mt][i];
}

__global__ __launch_bounds__(256, 2)
void flow_fused_k(const float* __restrict__ zin, float* __restrict__ zout,
                  __nv_bfloat16* __restrict__ zkout,
                  const float* __restrict__ fpk,
                  const float* __restrict__ sb1, const float* __restrict__ sb2,
                  const float* __restrict__ tb1, const float* __restrict__ tb2,
                  int inverse) {
    extern __shared__ float sm[];

    const int tid = threadIdx.x, wid = tid >> 5, lane = tid & 31;
    const int g = lane >> 2, j = lane & 3;
    const int wm = wid & 1, wn = wid >> 1;
    const size_t row0 = (size_t)blockIdx.x * 64;
    const uint32_t smb = smem_u32(sm);

    #pragma unroll
    for (int c = 0; c < 4; c++) {
        int idx = c * 256 + tid;
        int r = idx >> 4, seg = idx & 15;
        cpasync16(smb + (uint32_t)((F_Z + r * 68 + seg * 4) << 2),
                  zin + (row0 + r) * DIM + seg * 4);
    }
    const int layer0 = inverse ? NLAYERS - 1 : 0;
    flow_stage_w1(smb, fpk + layer0 * 16384, tid);
    flow_stage_w2(smb, fpk + layer0 * 16384 + 4096, tid);
    cp_commit();

    for (int idx = tid; idx < NLAYERS * HF; idx += 256) {
        sm[F_B1 + idx]       = sb1[idx];
        sm[F_B1 + 768 + idx] = tb1[idx];
    }
    if (tid < NLAYERS * QD) {
        sm[F_B2 + tid]       = sb2[tid];
        sm[F_B2 + 192 + tid] = tb2[tid];
    }

    cp_wait<0>();
    __syncthreads();
    flow_split(sm, tid, (layer0 & 1) ? QD : 0);
    __syncthreads();

    float res_s[2][4], res_t[2][4];

    #pragma unroll 1
    for (int p = 0; p < 2 * NLAYERS; p++) {
        const int lidx  = p >> 1, st = p & 1;
        const int layer = inverse ? NLAYERS - 1 - lidx : lidx;
        const int lnext = inverse ? NLAYERS - 1 - ((p + 1) >> 1) : ((p + 1) >> 1);
        const float* wnext = fpk + lnext * 16384 + ((p + 1) & 1) * 8192;
        const int b1off = F_B1 + st * 768 + layer * HF;

        flow_mma1(sm, smb, wm, wn, g, j, b1off);
        __syncthreads();
        if (p + 1 < 2 * NLAYERS) flow_stage_w1(smb, wnext, tid);
        cp_commit();
        cp_wait<1>();
        __syncthreads();
        float rtmp[2][4];
        flow_mma2(smb, wm, wn, g, j, rtmp);
        #pragma unroll
        for (int mt = 0; mt < 2; mt++)
            #pragma unroll
            for (int i = 0; i < 4; i++) {
                if (st == 0) res_s[mt][i] = rtmp[mt][i];
                else         res_t[mt][i] = rtmp[mt][i];
            }
        __syncthreads();
        if (p + 1 < 2 * NLAYERS) flow_stage_w2(smb, wnext + 4096, tid);
        cp_commit();

        if (st == 1) {
            const int moff = (layer & 1) ? 0 : QD;
            const int c0 = wn * 8 + 2 * j;
            float sb0 = sm[F_B2 + layer * QD + c0];
            float sb1v = sm[F_B2 + layer * QD + c0 + 1];
            float tb0 = sm[F_B2 + 192 + layer * QD + c0];
            float tb1v = sm[F_B2 + 192 + layer * QD + c0 + 1];
            #pragma unroll
            for (int mt = 0; mt < 2; mt++) {
                int r0 = wm * 32 + mt * 16 + g;
                float s0 = tanhf(res_s[mt][0] + sb0);
                float s1 = tanhf(res_s[mt][1] + sb1v);
                float s2 = tanhf(res_s[mt][2] + sb0);
                float s3 = tanhf(res_s[mt][3] + sb1v);
                float t0 = res_t[mt][0] + tb0;
                float t1 = res_t[mt][1] + tb1v;
                float t2 = res_t[mt][2] + tb0;
                float t3 = res_t[mt][3] + tb1v;
                float* z0 = &sm[F_Z + r0 * 68 + moff + c0];
                float* z1 = &sm[F_Z + (r0 + 8) * 68 + moff + c0];
                if (inverse) {
                    z0[0] = (z0[0] - t0) * __expf(-s0);
                    z0[1] = (z0[1] - t1) * __expf(-s1);
                    z1[0] = (z1[0] - t2) * __expf(-s2);
                    z1[1] = (z1[1] - t3) * __expf(-s3);
                } else {
                    z0[0] = fmaf(z0[0], __expf(s0), t0);
                    z0[1] = fmaf(z0[1], __expf(s1), t1);
                    z1[0] = fmaf(z1[0], __expf(s2), t2);
                    z1[1] = fmaf(z1[1], __expf(s3), t3);
                }
            }
        }

        if (p + 1 < 2 * NLAYERS) {
            cp_wait<1>();
            __syncthreads();
            if (st == 1) {
                flow_split(sm, tid, (lnext & 1) ? QD : 0);
                __syncthreads();
            }
        }
    }

    cp_wait<0>();
    __syncthreads();

    #pragma unroll
    for (int c = 0; c < 4; c++) {
        int idx = c * 256 + tid;
        int r = idx >> 4, seg = idx & 15;
        const float* zp = &sm[F_Z + r * 68 + seg * 4];
        float4 v = make_float4(zp[0], zp[1], zp[2], zp[3]);
        *reinterpret_cast<float4*>(zout + (row0 + r) * DIM + seg * 4) = v;
        if (zkout) {
            __nv_bfloat162 a, b;
            a.x = __float2bfloat16(v.x); a.y = __float2bfloat16(v.y);
            b.x = __float2bfloat16(v.z); b.y = __float2bfloat16(v.w);
            int kb = seg * 4;
            *reinterpret_cast<__nv_bfloat162*>(
                zkout + (row0 + r) * DIM + ipos(kb))     = a;
            *reinterpret_cast<__nv_bfloat162*>(
                zkout + (row0 + r) * DIM + ipos(kb + 2)) = b;
        }
    }
}

// ===========================================================================
// Shared GEMM epilogue (interleaved stores; EPI0 softplus, EPI1 sigmoid,
// EPI2 sigma(a1) recovery)
// ===========================================================================
template<int EPI, int NT>
__device__ __forceinline__ void gemm_epilogue(
    float acc[2][NT][4], size_t row0, int col0, int wm, int wn, int WN,
    int lane, const float* bia, const float* w3, const __nv_bfloat16* aux,
    char* Cc, int Nld) {
    #pragma unroll
    for (int mt = 0; mt < 2; mt++) {
        const size_t r0 = row0 + wm * 32 + mt * 16 + (lane >> 2);
        const size_t r1 = r0 + 8;
        #pragma unroll
        for (int nt = 0; nt < NT; nt++) {
            const int gc = col0 + wn * WN + nt * 8 + (lane & 3) * 2;
            const int gp = ipos(gc);
            float v0 = acc[mt][nt][0], v1 = acc[mt][nt][1];
            float v2 = acc[mt][nt][2], v3 = acc[mt][nt][3];
            if (EPI == 0) {
                float b0 = bia[gc], b1 = bia[gc + 1];
                v0 = softplus_fast(v0 + b0); v1 = softplus_fast(v1 + b1);
                v2 = softplus_fast(v2 + b0); v3 = softplus_fast(v3 + b1);
            } else if (EPI == 1) {
                float b0 = bia[gc], b1 = bia[gc + 1];
                float s0 = w3[gc], s1 = w3[gc + 1];
                v0 = s0 / (1.f + __expf(-(v0 + b0)));
                v1 = s1 / (1.f + __expf(-(v1 + b1)));
                v2 = s0 / (1.f + __expf(-(v2 + b0)));
                v3 = s1 / (1.f + __expf(-(v3 + b1)));
            } else if (EPI == 2) {
                __nv_bfloat162 h0 = *reinterpret_cast<const __nv_bfloat162*>(
                    aux + r0 * HH + gp);
                __nv_bfloat162 h1 = *reinterpret_cast<const __nv_bfloat162*>(
                    aux + r1 * HH + gp);
                v0 *= (1.f - __expf(-__bfloat162float(h0.x)));
                v1 *= (1.f - __expf(-__bfloat162float(h0.y)));
                v2 *= (1.f - __expf(-__bfloat162float(h1.x)));
                v3 *= (1.f - __expf(-__bfloat162float(h1.y)));
            }
            __nv_bfloat162 o0; o0.x = __float2bfloat16(v0); o0.y = __float2bfloat16(v1);
            __nv_bfloat162 o1; o1.x = __float2bfloat16(v2); o1.y = __float2bfloat16(v3);
            *reinterpret_cast<__nv_bfloat162*>(
                (__nv_bfloat16*)Cc + r0 * Nld + gp) = o0;
            *reinterpret_cast<__nv_bfloat162*>(
                (__nv_bfloat16*)Cc + r1 * Nld + gp) = o1;
        }
    }
}

// ===========================================================================
// Single-shot warp-MMA GEMM (K=64): stages zk tile ONCE + full W1 (256 rows),
// computes BOTH column blocks per CTA. smem 61,440 B -> 2 CTAs/SM.
// ===========================================================================
template<int K, int BN, int EPI>
__global__ __launch_bounds__(256, 2)
void gemm_mma(const __nv_bfloat16* __restrict__ A0, const __nv_bfloat16* __restrict__ A1,
              const __nv_bfloat16* __restrict__ B0, const __nv_bfloat16* __restrict__ B1,
              const float* __restrict__ bias0, const float* __restrict__ bias1,
              const float* __restrict__ w30,  const float* __restrict__ w31,
              const __nv_bfloat16* __restrict__ aux0, const __nv_bfloat16* __restrict__ aux1,
              void* __restrict__ C0, void* __restrict__ C1, int Nld) {
    constexpr int LDE = K + 16;           // 80 elems; 160B row ≡ 8 words mod 32
    extern __shared__ __align__(16) char smraw[];
    __nv_bfloat16* smA = reinterpret_cast<__nv_bfloat16*>(smraw);   // [128][LDE]
    __nv_bfloat16* smB = smA + 128 * LDE;                           // [256][LDE]

    const int tid = threadIdx.x, wid = tid >> 5, lane = tid & 31;
    const int zi = blockIdx.z;
    const __nv_bfloat16* A   = zi ? A1 : A0;
    const __nv_bfloat16* Bw  = zi ? B1 : B0;
    const float* bia         = zi ? bias1 : bias0;
    const float* w3          = zi ? w31 : w30;
    const __nv_bfloat16* aux = zi ? aux1 : aux0;
    char* Cc                 = (char*)(zi ? C1 : C0);

    const size_t row0 = (size_t)blockIdx.x * 128;

    constexpr int ASEG = K / 8;
    #pragma unroll 4
    for (int c = tid; c < 128 * ASEG; c += 256) {
        int r = c / ASEG, s = c % ASEG;
        *reinterpret_cast<uint4*>(smA + r * LDE + s * 8) =
            *reinterpret_cast<const uint4*>(A + (row0 + r) * K + s * 8);
    }
    #pragma unroll 8
    for (int c = tid; c < 256 * ASEG; c += 256) {
        int r = c / ASEG, s = c % ASEG;
        *reinterpret_cast<uint4*>(smB + r * LDE + s * 8) =
            *reinterpret_cast<const uint4*>(Bw + (size_t)r * K + s * 8);
    }
    __syncthreads();

    const int wm = wid & 3;
    const int wn = wid >> 2;
    constexpr int WN = BN / 2;
    constexpr int NT = WN / 8;
    const int g = lane >> 2;
    const int j = lane & 3;

    const uint32_t sA = smem_u32(smA), sB = smem_u32(smB);
    uint32_t aBase[2];
    #pragma unroll
    for (int mt = 0; mt < 2; mt++)
        aBase[mt] = sA + (uint32_t)((wm * 32 + mt * 16 + g) * LDE * 2 + j * 8);
    constexpr uint32_t ROW8 = (uint32_t)(8 * LDE * 2);

    #pragma unroll 1
    for (int cb = 0; cb < 2; cb++) {
        float acc[2][NT][4];
        #pragma unroll
        for (int mt = 0; mt < 2; mt++)
            #pragma unroll
            for (int nt = 0; nt < NT; nt++)
                #pragma unroll
                for (int i = 0; i < 4; i++) acc[mt][nt][i] = 0.f;

        uint32_t bBase[NT];
        #pragma unroll
        for (int nt = 0; nt < NT; nt++)
            bBase[nt] = sB + (uint32_t)((cb * BN + wn * WN + nt * 8 + g) * LDE * 2 + j * 8);

        #pragma unroll 4
        for (int kc = 0; kc < K / 16; kc++) {
            const uint32_t kb = (uint32_t)(kc * 32);
            uint32_t a[2][4];
            #pragma unroll
            for (int mt = 0; mt < 2; mt++) {
                lds64(aBase[mt] + kb,        a[mt][0], a[mt][2]);
                lds64(aBase[mt] + kb + ROW8, a[mt][1], a[mt][3]);
            }
            uint32_t b[NT][2];
            #pragma unroll
            for (int nt = 0; nt < NT; nt++)
                lds64(bBase[nt] + kb, b[nt][0], b[nt][1]);
            #pragma unroll
            for (int mt = 0; mt < 2; mt++)
                #pragma unroll
                for (int nt = 0; nt < NT; nt++)
                    mma16816(acc[mt][nt], a[mt][0], a[mt][1], a[mt][2], a[mt][3],
                             b[nt][0], b[nt][1]);
        }

        gemm_epilogue<EPI, NT>(acc, row0, cb * BN, wm, wn, WN, lane, bia, w3, aux, Cc, Nld);
    }
}

// ===========================================================================
// cp.async 2-stage pipelined warp-MMA GEMM (K = 256, BK = 64, LDE = 80).
// Column block in blockIdx.x LSB -> both col-blocks of the same A tile are
// wave-adjacent (second A read L2-hits).
// ===========================================================================
template<int K, int BN, int EPI>
__global__ __launch_bounds__(256, 2)
void gemm_pipe(const __nv_bfloat16* __restrict__ A0, const __nv_bfloat16* __restrict__ A1,
               const __nv_bfloat16* __restrict__ B0, const __nv_bfloat16* __restrict__ B1,
               const float* __restrict__ bias0, const float* __restrict__ bias1,
               const float* __restrict__ w30,  const float* __restrict__ w31,
               const __nv_bfloat16* __restrict__ aux0, const __nv_bfloat16* __restrict__ aux1,
               void* __restrict__ C0, void* __restrict__ C1, int Nld) {
    constexpr int BK   = 64;
    constexpr int LDE  = BK + 16;
    constexpr int NSTG = 2;
    constexpr int NCH  = K / BK;
    constexpr int STGE = (128 + BN) * LDE;
    extern __shared__ __align__(16) __nv_bfloat16 smp[];

    const int tid = threadIdx.x, wid = tid >> 5, lane = tid & 31;
    const int zi = blockIdx.z;
    const __nv_bfloat16* A   = zi ? A1 : A0;
    const __nv_bfloat16* Bw  = zi ? B1 : B0;
    const float* bia         = zi ? bias1 : bias0;
    const float* w3          = zi ? w31 : w30;
    const __nv_bfloat16* aux = zi ? aux1 : aux0;
    char* Cc                 = (char*)(zi ? C1 : C0);

    const size_t row0 = (size_t)(blockIdx.x >> 1) * 128;
    const int    col0 = (blockIdx.x & 1) * BN;
    const uint32_t sm0 = smem_u32(smp);

    auto load_chunk = [&](int s, int c) {
        const uint32_t dstS = sm0 + (uint32_t)(s * STGE * 2);
        const int k0 = c * BK;
        #pragma unroll
        for (int t = tid; t < (128 + BN) * 8; t += 256) {
            int r = t >> 3, seg = t & 7;
            if (r < 128) {
                cpasync16(dstS + (uint32_t)((r * LDE + seg * 8) * 2),
                          A + (row0 + r) * K + k0 + seg * 8);
            } else {
                int rb = r - 128;
                cpasync16(dstS + (uint32_t)(((128 + rb) * LDE + seg * 8) * 2),
                          Bw + (size_t)(col0 + rb) * K + k0 + seg * 8);
            }
        }
    };

    const int wm = wid & 3;
    const int wn = wid >> 2;
    constexpr int WN = BN / 2;
    constexpr int NT = WN / 8;
    const int g = lane >> 2;
    const int j = lane & 3;

    float acc[2][NT][4];
    #pragma unroll
    for (int mt = 0; mt < 2; mt++)
        #pragma unroll
        for (int nt = 0; nt < NT; nt++)
            #pragma unroll
            for (int i = 0; i < 4; i++) acc[mt][nt][i] = 0.f;

    uint32_t aBase[2];
    #pragma unroll
    for (int mt = 0; mt < 2; mt++)
        aBase[mt] = sm0 + (uint32_t)((wm * 32 + mt * 16 + g) * LDE * 2 + j * 8);
    uint32_t bBase[NT];
    #pragma unroll
    for (int nt = 0; nt < NT; nt++)
        bBase[nt] = sm0 + (uint32_t)((128 + wn * WN + nt * 8 + g) * LDE * 2 + j * 8);
    constexpr uint32_t ROW8 = (uint32_t)(8 * LDE * 2);

    load_chunk(0, 0); cp_commit();
    load_chunk(1, 1); cp_commit();

    for (int c = 0; c < NCH; c++) {
        cp_wait<1>();
        __syncthreads();
        const uint32_t soff = (uint32_t)((c % NSTG) * STGE * 2);
        #pragma unroll
        for (int kc = 0; kc < BK / 16; kc++) {
            const uint32_t kb = soff + (uint32_t)(kc * 32);
            uint32_t a[2][4];
            #pragma unroll
            for (int mt = 0; mt < 2; mt++) {
                lds64(aBase[mt] + kb,        a[mt][0], a[mt][2]);
                lds64(aBase[mt] + kb + ROW8, a[mt][1], a[mt][3]);
            }
            uint32_t b[NT][2];
            #pragma unroll
            for (int nt = 0; nt < NT; nt++)
                lds64(bBase[nt] + kb, b[nt][0], b[nt][1]);
            #pragma unroll
            for (int mt = 0; mt < 2; mt++)
                #pragma unroll
                for (int nt = 0; nt < NT; nt++)
                    mma16816(acc[mt][nt], a[mt][0], a[mt][1], a[mt][2], a[mt][3],
                             b[nt][0], b[nt][1]);
        }
        __syncthreads();
        if (c + 2 < NCH) load_chunk((c + 2) % NSTG, c + 2);
        cp_commit();
    }

    gemm_epilogue<EPI, NT>(acc, row0, col0, wm, wn, WN, lane, bia, w3, aux, Cc, Nld);
}

// ===========================================================================
// Fused final GEMM (K=512: [g1T | g1V] @ BMcat^T) + RK4 epilogue.
// ===========================================================================
__global__ __launch_bounds__(256, 2)
void gemm_rk4(const __nv_bfloat16* __restrict__ g1T, const __nv_bfloat16* __restrict__ g1V,
              const __nv_bfloat16* __restrict__ Bw,
              const float* __restrict__ u, const float* __restrict__ Bc,
              const float* __restrict__ zg, float* __restrict__ accg,
              __nv_bfloat16* __restrict__ zk, float* __restrict__ outg, int stage) {
    constexpr int BK   = 64;
    constexpr int LDE  = BK + 16;
    constexpr int NSTG = 3;
    constexpr int NCH  = 8;
    constexpr int BN   = 64;
    constexpr int STGE = (128 + BN) * LDE;
    extern __shared__ __align__(16) __nv_bfloat16 smp[];

    const int tid = threadIdx.x, wid = tid >> 5, lane = tid & 31;
    const size_t row0 = (size_t)blockIdx.x * 128;
    const uint32_t sm0 = smem_u32(smp);

    auto load_chunk = [&](int s, int c) {
        const uint32_t dstS = sm0 + (uint32_t)(s * STGE * 2);
        const __nv_bfloat16* A = (c < 4) ? g1T : g1V;
        const int k0 = (c & 3) * BK;
        #pragma unroll
        for (int t = tid; t < (128 + BN) * 8; t += 256) {
            int r = t >> 3, seg = t & 7;
            if (r < 128) {
                cpasync16(dstS + (uint32_t)((r * LDE + seg * 8) * 2),
                          A + (row0 + r) * HH + k0 + seg * 8);
            } else {
                int rb = r - 128;
                cpasync16(dstS + (uint32_t)(((128 + rb) * LDE + seg * 8) * 2),
                          Bw + (size_t)rb * 512 + c * BK + seg * 8);
            }
        }
    };

    const int wm = wid & 3;
    const int wn = wid >> 2;
    constexpr int WN = BN / 2;
    constexpr int NT = WN / 8;
    const int g = lane >> 2;
    const int j = lane & 3;

    float acc[2][NT][4];
    #pragma unroll
    for (int mt = 0; mt < 2; mt++)
        #pragma unroll
        for (int nt = 0; nt < NT; nt++)
            #pragma unroll
            for (int i = 0; i < 4; i++) acc[mt][nt][i] = 0.f;

    uint32_t aBase[2];
    #pragma unroll
    for (int mt = 0; mt < 2; mt++)
        aBase[mt] = sm0 + (uint32_t)((wm * 32 + mt * 16 + g) * LDE * 2 + j * 8);
    uint32_t bBase[NT];
    #pragma unroll
    for (int nt = 0; nt < NT; nt++)
        bBase[nt] = sm0 + (uint32_t)((128 + wn * WN + nt * 8 + g) * LDE * 2 + j * 8);
    constexpr uint32_t ROW8 = (uint32_t)(8 * LDE * 2);

    load_chunk(0, 0); cp_commit();
    load_chunk(1, 1); cp_commit();

    for (int c = 0; c < NCH; c++) {
        cp_wait<1>();
        __syncthreads();
        const uint32_t soff = (uint32_t)((c % NSTG) * STGE * 2);
        #pragma unroll
        for (int kc = 0; kc < BK / 16; kc++) {
            const uint32_t kb = soff + (uint32_t)(kc * 32);
            uint32_t a[2][4];
            #pragma unroll
            for (int mt = 0; mt < 2; mt++) {
                lds64(aBase[mt] + kb,        a[mt][0], a[mt][2]);
                lds64(aBase[mt] + kb + ROW8, a[mt][1], a[mt][3]);
            }
            uint32_t b[NT][2];
            #pragma unroll
            for (int nt = 0; nt < NT; nt++)
                lds64(bBase[nt] + kb, b[nt][0], b[nt][1]);
            #pragma unroll
            for (int mt = 0; mt < 2; mt++)
                #pragma unroll
                for (int nt = 0; nt < NT; nt++)
                    mma16816(acc[mt][nt], a[mt][0], a[mt][1], a[mt][2], a[mt][3],
                             b[nt][0], b[nt][1]);
        }
        __syncthreads();
        if (c + 2 < NCH) load_chunk((c + 2) % NSTG, c + 2);
        cp_commit();
    }

    const float wgt = (stage == 1 || stage == 2) ? 2.f : 1.f;
    const float cn  = (stage == 2) ? DTC : 0.5f * DTC;
    #pragma unroll
    for (int mt = 0; mt < 2; mt++) {
        const size_t r0 = row0 + wm * 32 + mt * 16 + (lane >> 2);
        const size_t r1 = r0 + 8;
        const float u0 = u[r0], u1 = u[r1];
        #pragma unroll
        for (int nt = 0; nt < NT; nt++) {
            const int gc = wn * WN + nt * 8 + (lane & 3) * 2;
            float dz0 = acc[mt][nt][0], dz1 = acc[mt][nt][1];
            float dz2 = acc[mt][nt][2], dz3 = acc[mt][nt][3];
            if (gc >= QD) {
                float bc0 = Bc[gc - QD], bc1 = Bc[gc - QD + 1];
                dz0 = fmaf(u0, bc0, dz0); dz1 = fmaf(u0, bc1, dz1);
                dz2 = fmaf(u1, bc0, dz2); dz3 = fmaf(u1, bc1, dz3);
            }
            const size_t i0 = r0 * DIM + gc, i1 = r1 * DIM + gc;
            float2 ap0 = make_float2(0.f, 0.f), ap1 = make_float2(0.f, 0.f);
            if (stage != 0) {
                ap0 = *reinterpret_cast<float2*>(accg + i0);
                ap1 = *reinterpret_cast<float2*>(accg + i1);
            }
            float a0 = fmaf(wgt, dz0, ap0.x), a1 = fmaf(wgt, dz1, ap0.y);
            float a2 = fmaf(wgt, dz2, ap1.x), a3 = fmaf(wgt, dz3, ap1.y);
            *reinterpret_cast<float2*>(accg + i0) = make_float2(a0, a1);
            *reinterpret_cast<float2*>(accg + i1) = make_float2(a2, a3);
            float2 z0 = *reinterpret_cast<const float2*>(zg + i0);
            float2 z1 = *reinterpret_cast<const float2*>(zg + i1);
            if (stage < 3) {
                const int gp = ipos(gc);
                __nv_bfloat162 o0, o1;
                o0.x = __float2bfloat16(fmaf(cn, dz0, z0.x));
                o0.y = __float2bfloat16(fmaf(cn, dz1, z0.y));
                o1.x = __float2bfloat16(fmaf(cn, dz2, z1.x));
                o1.y = __float2bfloat16(fmaf(cn, dz3, z1.y));
                *reinterpret_cast<__nv_bfloat162*>(zk + r0 * DIM + gp) = o0;
                *reinterpret_cast<__nv_bfloat162*>(zk + r1 * DIM + gp) = o1;
            } else {
                *reinterpret_cast<float2*>(outg + i0) =
                    make_float2(fmaf(DTC / 6.f, a0, z0.x), fmaf(DTC / 6.f, a1, z0.y));
                *reinterpret_cast<float2*>(outg + i1) =
                    make_float2(fmaf(DTC / 6.f, a2, z1.x), fmaf(DTC / 6.f, a3, z1.y));
            }
        }
    }
}

// ===========================================================================
// Host orchestration
// ===========================================================================
extern "C" void kernel_launch(void* const* d_in, const int* in_sizes, int n_in,
                              void* d_out, int out_size) {
    const float* h    = (const float*)d_in[0];
    const float* u    = (const float*)d_in[1];
    const float* sW1  = (const float*)d_in[2];
    const float* sb1  = (const float*)d_in[3];
    const float* sW2  = (const float*)d_in[4];
    const float* sb2  = (const float*)d_in[5];
    const float* tW1  = (const float*)d_in[6];
    const float* tb1  = (const float*)d_in[7];
    const float* tW2  = (const float*)d_in[8];
    const float* tb2  = (const float*)d_in[9];
    const float* kW1  = (const float*)d_in[10];
    const float* kb1  = (const float*)d_in[11];
    const float* kW2  = (const float*)d_in[12];
    const float* kb2  = (const float*)d_in[13];
    const float* kW3  = (const float*)d_in[14];
    const float* vW1  = (const float*)d_in[16];
    const float* vb1  = (const float*)d_in[17];
    const float* vW2  = (const float*)d_in[18];
    const float* vb2  = (const float*)d_in[19];
    const float* vW3  = (const float*)d_in[20];
    const float* A    = (const float*)d_in[22];
    const float* Lp   = (const float*)d_in[23];
    const float* Bc   = (const float*)d_in[24];
    float* out = (float*)d_out;

    float *z, *acc, *Mp, *fpk;
    __nv_bfloat16 *zk, *h1T, *h1V, *g2T, *g2V, *g1T, *g1V;
    __nv_bfloat16 *Bk1, *Bv1, *Bk2, *Bv2, *Bk2t, *Bv2t, *BMcat;
    cudaGetSymbolAddress((void**)&z,     g_z);
    cudaGetSymbolAddress((void**)&acc,   g_acc);
    cudaGetSymbolAddress((void**)&zk,    g_zk);
    cudaGetSymbolAddress((void**)&h1T,   g_h1T);
    cudaGetSymbolAddress((void**)&h1V,   g_h1V);
    cudaGetSymbolAddress((void**)&g2T,   g_g2T);
    cudaGetSymbolAddress((void**)&g2V,   g_g2V);
    cudaGetSymbolAddress((void**)&g1T,   g_g1T);
    cudaGetSymbolAddress((void**)&g1V,   g_g1V);
    cudaGetSymbolAddress((void**)&Bk1,   g_Bk1);
    cudaGetSymbolAddress((void**)&Bv1,   g_Bv1);
    cudaGetSymbolAddress((void**)&Bk2,   g_Bk2);
    cudaGetSymbolAddress((void**)&Bv2,   g_Bv2);
    cudaGetSymbolAddress((void**)&Bk2t,  g_Bk2t);
    cudaGetSymbolAddress((void**)&Bv2t,  g_Bv2t);
    cudaGetSymbolAddress((void**)&BMcat, g_BMcat);
    cudaGetSymbolAddress((void**)&Mp,    g_M);
    cudaGetSymbolAddress((void**)&fpk,   g_fpk);

    const int SM1    = (128 + 256) * 80 * 2;           //  61,440 (A + full W1)
    const int SMP128 = 2 * (128 + 128) * 80 * 2;       //  81,920
    const int SMP64  = 3 * (128 + 64)  * 80 * 2;       //  92,160
    const int SMF    = F_TOT * 4;                      // 112,640
    cudaFuncSetAttribute(gemm_mma<64, 128, 0>,
                         cudaFuncAttributeMaxDynamicSharedMemorySize, SM1);
    cudaFuncSetAttribute(gemm_pipe<256, 128, 1>,
                         cudaFuncAttributeMaxDynamicSharedMemorySize, SMP128);
    cudaFuncSetAttribute(gemm_pipe<256, 128, 2>,
                         cudaFuncAttributeMaxDynamicSharedMemorySize, SMP128);
    cudaFuncSetAttribute(gemm_rk4,
                         cudaFuncAttributeMaxDynamicSharedMemorySize, SMP64);
    cudaFuncSetAttribute(flow_fused_k,
                         cudaFuncAttributeMaxDynamicSharedMemorySize, SMF);

    // ---- prep: 2 launches ----
    build_M_k<<<1, 256>>>(A, Lp, Mp);
    prep_pack_k<<<dim3(384, 9), 256>>>(kW1, vW1, kW2, vW2, Mp,
                                       sW1, sW2, tW1, tW2,
                                       Bk1, Bv1, Bk2, Bv2, Bk2t, Bv2t,
                                       BMcat, fpk);

    // ---- s = flow_fwd(h) ----
    flow_fused_k<<<BATCH / 64, 256, SMF>>>(h, z, zk, fpk, sb1, sb2, tb1, tb2, 0);

    // ---- RK4 stages ----
    dim3 gS1(BATCH / 128, 1, 2);    // gemm1: both col-blocks per CTA, (T,V) on z
    dim3 gBig(BATCH / 64, 1, 2);    // pipes: col-block in x LSB, (T,V) on z
    for (int st = 0; st < 4; st++) {
        gemm_mma<64, 128, 0><<<gS1, 256, SM1>>>(
            zk, zk, Bk1, Bv1, kb1, vb1, 0, 0, 0, 0, h1T, h1V, HH);
        gemm_pipe<256, 128, 1><<<gBig, 256, SMP128>>>(
            h1T, h1V, Bk2, Bv2, kb2, vb2, kW3, vW3, 0, 0, g2T, g2V, HH);
        gemm_pipe<256, 128, 2><<<gBig, 256, SMP128>>>(
            g2T, g2V, Bk2t, Bv2t, 0, 0, 0, 0, h1T, h1V, g1T, g1V, HH);
        gemm_rk4<<<BATCH / 128, 256, SMP64>>>(
            g1T, g1V, BMcat, u, Bc, z, acc, zk, out, st);
    }

    // ---- h_next = flow_inv(z_next) in place on out ----
    flow_fused_k<<<BATCH / 64, 256, SMF>>>(out, out, (__nv_bfloat16*)0,
                                           fpk, sb1, sb2, tb1, tb2, 1);
}